// round 2
// baseline (speedup 1.0000x reference)
#include <cuda_runtime.h>

// VIN_68401649156499  — packed-f32x2 Bellman iteration version
//
// r = conv(input, w_eff) + b_eff     (w_eff collapses the 150-ch hidden layer)
// qr_a = conv(r, w_q[a])             (precomputed, lives in SMEM [a][pair][tid])
// v0 = max_a qr_a
// 79x: v = max_a (qr_a + conv(v, w_w[a]))   -- FFMA2 (fma.rn.f32x2), SMEM double-buffer
// final q_a = qr_a + conv(v, w_w[a]); logits = q[b,:,sx,sy]
//
// 256 threads/CTA, thread t owns row y=t>>2, cols x0=(t&3)*16 .. x0+15 (8 pixel pairs).

#define RS 68               // v-plane row stride (floats); 272B == 16 mod 128 -> rows hit distinct banks
#define PR 66               // 64 + 2 halo rows
#define PLANE (PR * RS)     // 4488 floats
#define NPIX 4096
typedef unsigned long long ull;

__device__ __forceinline__ ull pk(float lo, float hi) {
    ull r; asm("mov.b64 %0, {%1, %2};" : "=l"(r) : "f"(lo), "f"(hi)); return r;
}
__device__ __forceinline__ float2 up(ull v) {
    float2 r; asm("mov.b64 {%0, %1}, %2;" : "=f"(r.x), "=f"(r.y) : "l"(v)); return r;
}
__device__ __forceinline__ ull ffma2(ull a, ull b, ull c) {
    ull d; asm("fma.rn.f32x2 %0, %1, %2, %3;" : "=l"(d) : "l"(a), "l"(b), "l"(c)); return d;
}

// acc[a][p] = qr[a][pair p] + conv3x3(w_w[a], v)   for this thread's 16 pixels
__device__ __forceinline__ void bellman(ull acc[5][8], const float* __restrict__ vi,
                                        const ull* __restrict__ qrs, const ull* __restrict__ ww2,
                                        int y, int x0, int t) {
    #pragma unroll
    for (int a = 0; a < 5; ++a)
        #pragma unroll
        for (int p = 0; p < 8; ++p)
            acc[a][p] = qrs[(a * 8 + p) * 256 + t];          // lane-contiguous: conflict-free

    #pragma unroll
    for (int dy = 0; dy < 3; ++dy) {
        // V_k = v[y-1+dy][x0-1+k], k=0..17; plane col of pixel x is x+2
        const float* row = vi + (y + dy) * RS + x0 + 1;
        float2 e[8];
        #pragma unroll
        for (int j = 0; j < 8; ++j) e[j] = *(const float2*)(row + 1 + 2 * j);  // aligned LDS.64
        float va = row[0], vb = row[17];
        ull P[17];                                           // P_k = (V_k, V_{k+1})
        P[0] = pk(va, e[0].x);
        #pragma unroll
        for (int j = 0; j < 8; ++j) P[2 * j + 1] = pk(e[j].x, e[j].y);
        #pragma unroll
        for (int j = 0; j < 7; ++j) P[2 * j + 2] = pk(e[j].y, e[j + 1].x);
        P[16] = pk(e[7].y, vb);

        #pragma unroll
        for (int p = 0; p < 8; ++p) {
            #pragma unroll
            for (int dx = 0; dx < 3; ++dx) {
                ull vv = P[2 * p + dx];
                #pragma unroll
                for (int a = 0; a < 5; ++a)
                    acc[a][p] = ffma2(ww2[a * 9 + dy * 3 + dx], vv, acc[a][p]);
            }
        }
    }
}

__global__ __launch_bounds__(256, 1) void vin_kernel(
    const float* __restrict__ input,   // [128,2,64,64]
    const int*   __restrict__ coords,  // [128,4]
    const float* __restrict__ w_h,     // [150,2,3,3]
    const float* __restrict__ b_h,     // [150]
    const float* __restrict__ w_r,     // [1,150,1,1]
    const float* __restrict__ w_q,     // [5,1,3,3]
    const float* __restrict__ w_w,     // [5,1,3,3]
    float* __restrict__ out_q,         // [128,5,64,64]
    float* __restrict__ out_logits)    // [128,5]
{
    extern __shared__ float smem[];
    float* plane0 = smem;                      // PLANE floats
    float* plane1 = smem + PLANE;              // PLANE floats
    ull*   qrs    = (ull*)(smem + 2 * PLANE);  // 5*8*256 ull = 80KB (offset 35904B, 8B aligned)
    float* sweff  = (float*)(qrs + 5 * 8 * 256); // 19 floats

    const int b  = blockIdx.x;
    const int t  = threadIdx.x;
    const int y  = t >> 2;           // 0..63
    const int x0 = (t & 3) * 16;     // 0,16,32,48

    // ---- zero both padded planes (halo must stay zero forever) ----
    for (int k = t; k < 2 * PLANE; k += 256) smem[k] = 0.f;

    // ---- collapse hidden layer: weff[18], beff ----
    if (t < 18) {
        float s = 0.f;
        for (int c = 0; c < 150; ++c) s += w_r[c] * w_h[c * 18 + t];
        sweff[t] = s;
    } else if (t == 18) {
        float s = 0.f;
        for (int c = 0; c < 150; ++c) s += w_r[c] * b_h[c];
        sweff[18] = s;
    }
    __syncthreads();

    // ---- stage input channels into the two planes (interior at [y+1][x+2]) ----
    const float* inb = input + (size_t)b * 2 * NPIX;
    #pragma unroll
    for (int k = 0; k < 32; ++k) {
        int lin = k * 256 + t;               // 0..8191
        int li  = lin >> 12;
        int rem = lin & 4095;
        smem[li * PLANE + ((rem >> 6) + 1) * RS + (rem & 63) + 2] = inb[lin];
    }
    __syncthreads();

    // ---- r = conv(input, weff) + beff ----
    float weff[18];
    #pragma unroll
    for (int k = 0; k < 18; ++k) weff[k] = sweff[k];
    const float beff = sweff[18];

    float rv[16];
    #pragma unroll
    for (int i = 0; i < 16; ++i) {
        float s = beff;
        #pragma unroll
        for (int li = 0; li < 2; ++li)
            #pragma unroll
            for (int dy = 0; dy < 3; ++dy)
                #pragma unroll
                for (int dx = 0; dx < 3; ++dx)
                    s = fmaf(weff[li * 9 + dy * 3 + dx],
                             smem[li * PLANE + (y + dy) * RS + x0 + i + dx + 1], s);
        rv[i] = s;
    }
    __syncthreads();

    // ---- r -> plane0 interior ----
    #pragma unroll
    for (int i = 0; i < 16; ++i) plane0[(y + 1) * RS + x0 + i + 2] = rv[i];
    __syncthreads();

    // ---- qr_a = conv(r, w_q[a]); v0 = max_a qr ----
    float wq[45];
    #pragma unroll
    for (int k = 0; k < 45; ++k) wq[k] = w_q[k];

    float qr[5][16];
    #pragma unroll
    for (int i = 0; i < 16; ++i) {
        #pragma unroll
        for (int a = 0; a < 5; ++a) {
            float s = 0.f;
            #pragma unroll
            for (int dy = 0; dy < 3; ++dy)
                #pragma unroll
                for (int dx = 0; dx < 3; ++dx)
                    s = fmaf(wq[a * 9 + dy * 3 + dx],
                             plane0[(y + dy) * RS + x0 + i + dx + 1], s);
            qr[a][i] = s;
        }
        float v = qr[0][i];
        #pragma unroll
        for (int a = 1; a < 5; ++a) v = fmaxf(v, qr[a][i]);
        plane1[(y + 1) * RS + x0 + i + 2] = v;
    }

    // ---- qr -> SMEM packed [a][pair][tid] ----
    #pragma unroll
    for (int a = 0; a < 5; ++a)
        #pragma unroll
        for (int p = 0; p < 8; ++p)
            qrs[(a * 8 + p) * 256 + t] = pk(qr[a][2 * p], qr[a][2 * p + 1]);

    // ---- packed (w,w) iteration weights, register-resident ----
    ull ww2[45];
    #pragma unroll
    for (int k = 0; k < 45; ++k) { float w = w_w[k]; ww2[k] = pk(w, w); }
    __syncthreads();

    // ---- 79 Bellman iterations ----
    for (int it = 0; it < 79; ++it) {
        const float* vi = (it & 1) ? plane0 : plane1;
        float*       vo = (it & 1) ? plane1 : plane0;
        ull acc[5][8];
        bellman(acc, vi, qrs, ww2, y, x0, t);

        float* orow = vo + (y + 1) * RS + x0 + 2;
        #pragma unroll
        for (int p = 0; p < 8; ++p) {
            float2 m = up(acc[0][p]);
            #pragma unroll
            for (int a = 1; a < 5; ++a) {
                float2 q = up(acc[a][p]);
                m.x = fmaxf(m.x, q.x);
                m.y = fmaxf(m.y, q.y);
            }
            *(float2*)(orow + 2 * p) = m;      // aligned STS.64
        }
        __syncthreads();
    }

    // ---- final q (last iteration wrote plane0) ----
    ull acc[5][8];
    bellman(acc, plane0, qrs, ww2, y, x0, t);

    const int sx = coords[b * 4 + 0];
    const int sy = coords[b * 4 + 1];
    float* oq = out_q + (size_t)b * 5 * NPIX;

    #pragma unroll
    for (int a = 0; a < 5; ++a) {
        float2 f[8];
        #pragma unroll
        for (int p = 0; p < 8; ++p) f[p] = up(acc[a][p]);
        float* base = oq + a * NPIX + y * 64 + x0;
        #pragma unroll
        for (int g = 0; g < 4; ++g)
            *reinterpret_cast<float4*>(base + 4 * g) =
                make_float4(f[2 * g].x, f[2 * g].y, f[2 * g + 1].x, f[2 * g + 1].y);
    }

    if (y == sx && sy >= x0 && sy < x0 + 16) {
        int i = sy - x0;
        #pragma unroll
        for (int a = 0; a < 5; ++a) {
            float2 f = up(acc[a][i >> 1]);
            out_logits[b * 5 + a] = (i & 1) ? f.y : f.x;
        }
    }
}

extern "C" void kernel_launch(void* const* d_in, const int* in_sizes, int n_in,
                              void* d_out, int out_size) {
    const float* input  = (const float*)d_in[0];
    const int*   coords = (const int*)  d_in[1];
    const float* w_h    = (const float*)d_in[2];
    const float* b_h    = (const float*)d_in[3];
    const float* w_r    = (const float*)d_in[4];
    const float* w_q    = (const float*)d_in[5];
    const float* w_w    = (const float*)d_in[6];
    float* out = (float*)d_out;

    const int smem_bytes = 2 * PLANE * sizeof(float) + 5 * 8 * 256 * sizeof(ull) + 32 * sizeof(float);
    cudaFuncSetAttribute(vin_kernel, cudaFuncAttributeMaxDynamicSharedMemorySize, smem_bytes);
    vin_kernel<<<128, 256, smem_bytes>>>(input, coords, w_h, b_h, w_r, w_q, w_w,
                                         out, out + 128 * 5 * NPIX);
}